// round 11
// baseline (speedup 1.0000x reference)
#include <cuda_runtime.h>
#include <stdint.h>

#define NROWS   131072
#define DIM     128
#define QSTAGES 4
#define KCB     1024
#define BETA    0.25
#define BROWS   128            // rows per block
#define NTHR    256
#define CH      32             // dims per B chunk
#define NCH     (DIM / CH)     // 4 chunks

typedef unsigned long long u64;
#define UMAX64 0xFFFFFFFFFFFFFFFFull

// Scratch (allocation-free rule: __device__ globals)
__device__ float  g_resid[NROWS * DIM];
__device__ float  g_enorm[QSTAGES * KCB];
__device__ double g_loss[QSTAGES];

// Dynamic-smem layout: A resident all 128 dims; B double-buffered 32-dim chunks
struct Sh {
    float A[DIM][BROWS + 4];     // 67.6 KB  [dim][row]
    float B[2][CH][BROWS + 4];   // 33.8 KB  [buf][dim][cw]
    u64   Red[BROWS][9];         //  9.2 KB
    float rrS[BROWS];
    int   Ridx[BROWS];
    int   Ridx2[BROWS];
};

// ---------------------------------------------------------------------------
// packed fp32x2 helpers (Blackwell sm_100+)
// ---------------------------------------------------------------------------
__device__ __forceinline__ u64 pack2f(float lo, float hi) {
    u64 r; asm("mov.b64 %0, {%1, %2};" : "=l"(r) : "f"(lo), "f"(hi)); return r;
}
__device__ __forceinline__ void unpack2f(u64 v, float& lo, float& hi) {
    asm("mov.b64 {%0, %1}, %2;" : "=f"(lo), "=f"(hi) : "l"(v));
}
__device__ __forceinline__ void ffma2(u64& d, u64 a, u64 b) {
    asm("fma.rn.f32x2 %0, %1, %2, %0;" : "+l"(d) : "l"(a), "l"(b));
}
__device__ __forceinline__ unsigned int fkey(float f) {
    unsigned int u = __float_as_uint(f);
    return (u & 0x80000000u) ? ~u : (u | 0x80000000u);
}
__device__ __forceinline__ void top2(u64 k, u64& b0, u64& b1) {
    if (k < b0) { b1 = b0; b0 = k; }
    else if (k < b1) { b1 = k; }
}

// ---------------------------------------------------------------------------
__global__ void rvq_prep_kernel(const float* __restrict__ cb) {
    if (blockIdx.x == 0 && threadIdx.x < QSTAGES) g_loss[threadIdx.x] = 0.0;
    int wid  = (blockIdx.x * blockDim.x + threadIdx.x) >> 5;
    int lane = threadIdx.x & 31;
    if (wid >= QSTAGES * KCB) return;
    const float* row = cb + (size_t)wid * DIM;
    double s = 0.0;
#pragma unroll
    for (int i = 0; i < 4; i++) {
        double v = (double)row[lane + i * 32];
        s = fma(v, v, s);
    }
#pragma unroll
    for (int off = 16; off; off >>= 1) s += __shfl_down_sync(0xffffffffu, s, off);
    if (lane == 0) g_enorm[wid] = (float)s;
}

// ---------------------------------------------------------------------------
// One RVQ stage. 256 threads, 128x128 tile, 2 blocks/SM (smem-limited).
// A is staged into smem ONCE (fused with the rr pre-pass); the 8-tile
// mainloop only stages B (32-dim double-buffered chunks, 1 sync each).
// Warp = one 16-cw group x all 128 rows; thread = 4 rows x 16 cw; acc packs
// cw-pairs so B fragments are natural u64s from warp-uniform LDS.128 and A
// is one lane-consecutive LDS.128 + 4 dup movs.
// ---------------------------------------------------------------------------
template <int STAGE>
__global__ __launch_bounds__(NTHR)
void rvq_stage_kernel(const float* __restrict__ x,
                      const float* __restrict__ cbq,
                      float* __restrict__ out)
{
    const float* cb  = cbq + (size_t)STAGE * KCB * DIM;
    const float* rin = (STAGE == 0) ? x : (const float*)g_resid;

    extern __shared__ __align__(16) char smem_raw[];
    Sh& sh = *reinterpret_cast<Sh*>(smem_raw);

    const int tid  = threadIdx.x;
    const int m0   = blockIdx.x * BROWS;
    const int lane = tid & 31;
    const int cwg  = tid >> 5;            // warp id = cw group 0..7 (16 cw each)
    const int rowb = lane * 4;            // first of this thread's 4 rows
    const int lcw  = tid & 127;           // B loader codeword
    const int lh   = (tid >> 7) * 16;     // B loader dim offset {0,16}

    // ---- fused pre-pass: stage A into smem + rr per row (double) ----
    {
        const int row = tid >> 1;
        const int h   = (tid & 1) * 64;
        const float* rv = rin + (size_t)(m0 + row) * DIM + h;
        double s = 0.0;
#pragma unroll
        for (int c = 0; c < 16; c++) {
            float4 v = *(const float4*)(rv + c * 4);
            sh.A[h + c * 4 + 0][row] = v.x;
            sh.A[h + c * 4 + 1][row] = v.y;
            sh.A[h + c * 4 + 2][row] = v.z;
            sh.A[h + c * 4 + 3][row] = v.w;
            s = fma((double)v.x, (double)v.x, s);
            s = fma((double)v.y, (double)v.y, s);
            s = fma((double)v.z, (double)v.z, s);
            s = fma((double)v.w, (double)v.w, s);
        }
        s += __shfl_xor_sync(0xffffffffu, s, 1);
        if ((tid & 1) == 0) sh.rrS[row] = (float)s;
    }
    __syncthreads();

    float rrv[4];
#pragma unroll
    for (int r = 0; r < 4; r++) rrv[r] = sh.rrS[rowb + r];

    u64 best0 = UMAX64, best1 = UMAX64;   // per-row global top2 (tid<128: row=tid)

    for (int nt = 0; nt < KCB / 128; nt++) {
        const int n0 = nt * 128;
        u64 acc2[4][8];                    // [row][cw-pair]
#pragma unroll
        for (int r = 0; r < 4; r++)
#pragma unroll
            for (int j = 0; j < 8; j++) acc2[r][j] = 0ull;

        const float* bBase = cb + (size_t)(n0 + lcw) * DIM + lh;

        // preload B chunk 0 into buffer 0 (conflict-free row-contiguous)
        {
#pragma unroll
            for (int q = 0; q < 4; q++) {
                float4 b = *(const float4*)(bBase + q * 4);
                sh.B[0][lh + q * 4 + 0][lcw] = b.x;
                sh.B[0][lh + q * 4 + 1][lcw] = b.y;
                sh.B[0][lh + q * 4 + 2][lcw] = b.z;
                sh.B[0][lh + q * 4 + 3][lcw] = b.w;
            }
        }
        __syncthreads();

#pragma unroll 1
        for (int ds = 0; ds < NCH; ds++) {
            const int cur = ds & 1, nxt = cur ^ 1;
            float4 bn[4];
            if (ds < NCH - 1) {
#pragma unroll
                for (int q = 0; q < 4; q++)
                    bn[q] = *(const float4*)(bBase + (ds + 1) * CH + q * 4);
            }
#pragma unroll 16
            for (int dd = 0; dd < CH; dd++) {
                // A: one lane-consecutive LDS.128 (4 rows), dup via 4 movs
                float4 af = *(const float4*)&sh.A[ds * CH + dd][rowb];
                u64 ad[4] = { pack2f(af.x, af.x), pack2f(af.y, af.y),
                              pack2f(af.z, af.z), pack2f(af.w, af.w) };
                // B: 4 warp-uniform LDS.128 -> 8 natural cw-pair u64s
                const ulonglong2* bp = (const ulonglong2*)&sh.B[cur][dd][cwg * 16];
                ulonglong2 b0 = bp[0], b1 = bp[1], b2 = bp[2], b3 = bp[3];
                u64 bb[8] = { b0.x, b0.y, b1.x, b1.y, b2.x, b2.y, b3.x, b3.y };
#pragma unroll
                for (int r = 0; r < 4; r++)
#pragma unroll
                    for (int j = 0; j < 8; j++)
                        ffma2(acc2[r][j], ad[r], bb[j]);
            }
            if (ds < NCH - 1) {
#pragma unroll
                for (int q = 0; q < 4; q++) {
                    sh.B[nxt][lh + q * 4 + 0][lcw] = bn[q].x;
                    sh.B[nxt][lh + q * 4 + 1][lcw] = bn[q].y;
                    sh.B[nxt][lh + q * 4 + 2][lcw] = bn[q].z;
                    sh.B[nxt][lh + q * 4 + 3][lcw] = bn[q].w;
                }
                __syncthreads();
            }
        }

        // ---- scores replicate reference ((rr - 2*dot) + ee); local top2 ----
        float en[16];
#pragma unroll
        for (int j = 0; j < 16; j++)
            en[j] = __ldg(&g_enorm[STAGE * KCB + n0 + cwg * 16 + j]);

        u64 pb0[4], pb1[4];
#pragma unroll
        for (int r = 0; r < 4; r++) {
            u64 x0 = UMAX64, x1 = UMAX64;
#pragma unroll
            for (int j = 0; j < 8; j++) {
                float dlo, dhi;
                unpack2f(acc2[r][j], dlo, dhi);
                float slo = (rrv[r] - 2.0f * dlo) + en[2 * j];
                float shi = (rrv[r] - 2.0f * dhi) + en[2 * j + 1];
                unsigned idx = (unsigned)(n0 + cwg * 16 + 2 * j);
                top2(((u64)fkey(slo) << 32) | idx,       x0, x1);
                top2(((u64)fkey(shi) << 32) | (idx + 1), x0, x1);
            }
            pb0[r] = x0; pb1[r] = x1;
        }

        // pass 1: per-stripe top1s -> global top1 t0 + 2nd-min-of-b0s t1
        __syncthreads();   // mainloop B reads done; Red safe to write
#pragma unroll
        for (int r = 0; r < 4; r++) sh.Red[rowb + r][cwg] = pb0[r];
        __syncthreads();
        u64 t0 = UMAX64, t1 = UMAX64; int sstar = 0;
        if (tid < 128) {
#pragma unroll
            for (int t = 0; t < 8; t++) top2(sh.Red[tid][t], t0, t1);
            sstar = (int)((t0 & 127u) >> 4);   // winner cw-group
        }
        __syncthreads();
        // pass 2: per-stripe runner-ups; exact top2 = min(t1, b1[winner])
#pragma unroll
        for (int r = 0; r < 4; r++) sh.Red[rowb + r][cwg] = pb1[r];
        __syncthreads();
        if (tid < 128) {
            u64 w = sh.Red[tid][sstar];
            if (w < t1) t1 = w;
            top2(t0, best0, best1);
            top2(t1, best0, best1);
        }
    }

    __syncthreads();
    if (tid < 128) {
        sh.Ridx[tid]  = (int)(best0 & 0xFFFFFFFFull);
        sh.Ridx2[tid] = (int)(best1 & 0xFFFFFFFFull);
    }
    __syncthreads();

    // ---- double-precision rescue + residual update + loss ----
    const int row = tid >> 1;
    const int h   = (tid & 1) * 64;
    const int i1  = sh.Ridx[row];
    const int i2  = sh.Ridx2[row];
    const float* rv = rin + (size_t)(m0 + row) * DIM + h;
    const float* e1 = cb + (size_t)i1 * DIM + h;
    const float* e2 = cb + (size_t)i2 * DIM + h;

    double d1 = 0.0, d2 = 0.0;
#pragma unroll
    for (int c = 0; c < 16; c++) {
        float4 r4 = *(const float4*)(rv + c * 4);
        float4 q1 = *(const float4*)(e1 + c * 4);
        float4 q2 = *(const float4*)(e2 + c * 4);
        d1 = fma((double)r4.x, (double)q1.x, d1);
        d1 = fma((double)r4.y, (double)q1.y, d1);
        d1 = fma((double)r4.z, (double)q1.z, d1);
        d1 = fma((double)r4.w, (double)q1.w, d1);
        d2 = fma((double)r4.x, (double)q2.x, d2);
        d2 = fma((double)r4.y, (double)q2.y, d2);
        d2 = fma((double)r4.z, (double)q2.z, d2);
        d2 = fma((double)r4.w, (double)q2.w, d2);
    }
    d1 += __shfl_xor_sync(0xffffffffu, d1, 1);
    d2 += __shfl_xor_sync(0xffffffffu, d2, 1);

    const float rr = sh.rrS[row];
    const float s1 = (rr - 2.0f * (float)d1) + __ldg(&g_enorm[STAGE * KCB + i1]);
    const float s2 = (rr - 2.0f * (float)d2) + __ldg(&g_enorm[STAGE * KCB + i2]);
    int cidx;
    if (s1 < s2)      cidx = i1;
    else if (s2 < s1) cidx = i2;
    else              cidx = (i1 < i2) ? i1 : i2;

    if ((tid & 1) == 0)
        out[(size_t)NROWS * DIM + 1 + (size_t)(m0 + row) * QSTAGES + STAGE] = (float)cidx;

    const float* qv = cb + (size_t)cidx * DIM + h;
    double lsum = 0.0;
#pragma unroll
    for (int c = 0; c < 16; c++) {
        float4 q = *(const float4*)(qv + c * 4);
        float4 r = *(const float4*)(rv + c * 4);
        float4 rn;
        rn.x = r.x - q.x; rn.y = r.y - q.y; rn.z = r.z - q.z; rn.w = r.w - q.w;
        lsum += (double)rn.x * rn.x + (double)rn.y * rn.y +
                (double)rn.z * rn.z + (double)rn.w * rn.w;
        if (STAGE < QSTAGES - 1) {
            *(float4*)(g_resid + (size_t)(m0 + row) * DIM + h + c * 4) = rn;
        } else {
            const float4 xx = *(const float4*)(x + (size_t)(m0 + row) * DIM + h + c * 4);
            float4 xq;
            xq.x = xx.x - rn.x; xq.y = xx.y - rn.y;
            xq.z = xx.z - rn.z; xq.w = xx.w - rn.w;
            *(float4*)(out + (size_t)(m0 + row) * DIM + h + c * 4) = xq;
        }
    }
#pragma unroll
    for (int off = 16; off; off >>= 1) lsum += __shfl_down_sync(0xffffffffu, lsum, off);
    if ((tid & 31) == 0) atomicAdd(&g_loss[STAGE], lsum);
}

// ---------------------------------------------------------------------------
__global__ void rvq_finalize_kernel(float* __restrict__ out) {
    if (threadIdx.x == 0) {
        double s = 0.0;
        for (int i = 0; i < QSTAGES; i++) s += g_loss[i];
        double mean = (1.0 + BETA) * s / ((double)NROWS * DIM) / (double)QSTAGES;
        out[(size_t)NROWS * DIM] = (float)mean;
    }
}

extern "C" void kernel_launch(void* const* d_in, const int* in_sizes, int n_in,
                              void* d_out, int out_size) {
    const float* x  = (const float*)d_in[0];
    const float* cb = (const float*)d_in[1];
    if (n_in >= 2 && in_sizes[0] == QSTAGES * KCB * DIM && in_sizes[1] == NROWS * DIM) {
        x  = (const float*)d_in[1];
        cb = (const float*)d_in[0];
    }
    float* out = (float*)d_out;

    const int shbytes = (int)sizeof(Sh);
    cudaFuncSetAttribute(rvq_stage_kernel<0>, cudaFuncAttributeMaxDynamicSharedMemorySize, shbytes);
    cudaFuncSetAttribute(rvq_stage_kernel<1>, cudaFuncAttributeMaxDynamicSharedMemorySize, shbytes);
    cudaFuncSetAttribute(rvq_stage_kernel<2>, cudaFuncAttributeMaxDynamicSharedMemorySize, shbytes);
    cudaFuncSetAttribute(rvq_stage_kernel<3>, cudaFuncAttributeMaxDynamicSharedMemorySize, shbytes);

    rvq_prep_kernel<<<512, 256>>>(cb);
    rvq_stage_kernel<0><<<NROWS / BROWS, NTHR, shbytes>>>(x, cb, out);
    rvq_stage_kernel<1><<<NROWS / BROWS, NTHR, shbytes>>>(x, cb, out);
    rvq_stage_kernel<2><<<NROWS / BROWS, NTHR, shbytes>>>(x, cb, out);
    rvq_stage_kernel<3><<<NROWS / BROWS, NTHR, shbytes>>>(x, cb, out);
    rvq_finalize_kernel<<<1, 32>>>(out);
}

// round 15
// speedup vs baseline: 1.0455x; 1.0455x over previous
#include <cuda_runtime.h>
#include <stdint.h>

#define NROWS   131072
#define DIM     128
#define QSTAGES 4
#define KCB     1024
#define BETA    0.25
#define BROWS   128            // rows per block
#define NTHR    256
#define CH      32             // dims per B chunk
#define NCH     (DIM / CH)     // 4 chunks

typedef unsigned long long u64;
#define UMAX64 0xFFFFFFFFFFFFFFFFull

// Scratch (allocation-free rule: __device__ globals)
__device__ float  g_resid[NROWS * DIM];
__device__ float  g_enorm[QSTAGES * KCB];
__device__ double g_loss[QSTAGES];

// Dynamic-smem layout: A resident all 128 dims; B double-buffered 32-dim chunks
struct Sh {
    float A[DIM][BROWS + 4];     // 67.6 KB  [dim][row]
    float B[2][CH][BROWS + 4];   // 33.8 KB  [buf][dim][cw]
    u64   Red[BROWS][9];         //  9.2 KB
    float rrS[BROWS];
    int   Ridx[BROWS];
    int   Ridx2[BROWS];
};

// ---------------------------------------------------------------------------
// packed fp32x2 helpers (Blackwell sm_100+)
// ---------------------------------------------------------------------------
__device__ __forceinline__ u64 pack2f(float lo, float hi) {
    u64 r; asm("mov.b64 %0, {%1, %2};" : "=l"(r) : "f"(lo), "f"(hi)); return r;
}
__device__ __forceinline__ void unpack2f(u64 v, float& lo, float& hi) {
    asm("mov.b64 {%0, %1}, %2;" : "=f"(lo), "=f"(hi) : "l"(v));
}
__device__ __forceinline__ void ffma2(u64& d, u64 a, u64 b) {
    asm("fma.rn.f32x2 %0, %1, %2, %0;" : "+l"(d) : "l"(a), "l"(b));
}
__device__ __forceinline__ unsigned int fkey(float f) {
    unsigned int u = __float_as_uint(f);
    return (u & 0x80000000u) ? ~u : (u | 0x80000000u);
}
__device__ __forceinline__ void top2(u64 k, u64& b0, u64& b1) {
    if (k < b0) { b1 = b0; b0 = k; }
    else if (k < b1) { b1 = k; }
}

// ---------------------------------------------------------------------------
__global__ void rvq_prep_kernel(const float* __restrict__ cb) {
    if (blockIdx.x == 0 && threadIdx.x < QSTAGES) g_loss[threadIdx.x] = 0.0;
    int wid  = (blockIdx.x * blockDim.x + threadIdx.x) >> 5;
    int lane = threadIdx.x & 31;
    if (wid >= QSTAGES * KCB) return;
    const float* row = cb + (size_t)wid * DIM;
    double s = 0.0;
#pragma unroll
    for (int i = 0; i < 4; i++) {
        double v = (double)row[lane + i * 32];
        s = fma(v, v, s);
    }
#pragma unroll
    for (int off = 16; off; off >>= 1) s += __shfl_down_sync(0xffffffffu, s, off);
    if (lane == 0) g_enorm[wid] = (float)s;
}

// ---------------------------------------------------------------------------
// One RVQ stage. 256 threads, 128x128 tile, 2 blocks/SM (forced via
// launch_bounds minBlocks=2 -> regs capped at 128). A is staged into smem
// ONCE (fused with the rr pre-pass); the 8-tile mainloop only stages B
// (32-dim double-buffered chunks, 1 sync each). Warp = one 16-cw group x
// all 128 rows; thread = 4 rows x 16 cw; acc packs cw-pairs so B fragments
// are natural u64s from warp-uniform LDS.128 and A is one lane-consecutive
// LDS.128 + 4 dup movs.
// ---------------------------------------------------------------------------
template <int STAGE>
__global__ __launch_bounds__(NTHR, 2)
void rvq_stage_kernel(const float* __restrict__ x,
                      const float* __restrict__ cbq,
                      float* __restrict__ out)
{
    const float* cb  = cbq + (size_t)STAGE * KCB * DIM;
    const float* rin = (STAGE == 0) ? x : (const float*)g_resid;

    extern __shared__ __align__(16) char smem_raw[];
    Sh& sh = *reinterpret_cast<Sh*>(smem_raw);

    const int tid  = threadIdx.x;
    const int m0   = blockIdx.x * BROWS;
    const int lane = tid & 31;
    const int cwg  = tid >> 5;            // warp id = cw group 0..7 (16 cw each)
    const int rowb = lane * 4;            // first of this thread's 4 rows
    const int lcw  = tid & 127;           // B loader codeword
    const int lh   = (tid >> 7) * 16;     // B loader dim offset {0,16}

    // ---- fused pre-pass: stage A into smem + rr per row (double) ----
    {
        const int row = tid >> 1;
        const int h   = (tid & 1) * 64;
        const float* rv = rin + (size_t)(m0 + row) * DIM + h;
        double s = 0.0;
#pragma unroll
        for (int c = 0; c < 16; c++) {
            float4 v = *(const float4*)(rv + c * 4);
            sh.A[h + c * 4 + 0][row] = v.x;
            sh.A[h + c * 4 + 1][row] = v.y;
            sh.A[h + c * 4 + 2][row] = v.z;
            sh.A[h + c * 4 + 3][row] = v.w;
            s = fma((double)v.x, (double)v.x, s);
            s = fma((double)v.y, (double)v.y, s);
            s = fma((double)v.z, (double)v.z, s);
            s = fma((double)v.w, (double)v.w, s);
        }
        s += __shfl_xor_sync(0xffffffffu, s, 1);
        if ((tid & 1) == 0) sh.rrS[row] = (float)s;
    }
    __syncthreads();

    float rrv[4];
#pragma unroll
    for (int r = 0; r < 4; r++) rrv[r] = sh.rrS[rowb + r];

    u64 best0 = UMAX64, best1 = UMAX64;   // per-row global top2 (tid<128: row=tid)

    for (int nt = 0; nt < KCB / 128; nt++) {
        const int n0 = nt * 128;
        u64 acc2[4][8];                    // [row][cw-pair]
#pragma unroll
        for (int r = 0; r < 4; r++)
#pragma unroll
            for (int j = 0; j < 8; j++) acc2[r][j] = 0ull;

        const float* bBase = cb + (size_t)(n0 + lcw) * DIM + lh;

        // preload B chunk 0 into buffer 0 (conflict-free row-contiguous)
        {
#pragma unroll
            for (int q = 0; q < 4; q++) {
                float4 b = *(const float4*)(bBase + q * 4);
                sh.B[0][lh + q * 4 + 0][lcw] = b.x;
                sh.B[0][lh + q * 4 + 1][lcw] = b.y;
                sh.B[0][lh + q * 4 + 2][lcw] = b.z;
                sh.B[0][lh + q * 4 + 3][lcw] = b.w;
            }
        }
        __syncthreads();

#pragma unroll 1
        for (int ds = 0; ds < NCH; ds++) {
            const int cur = ds & 1, nxt = cur ^ 1;
            float4 bn[4];
            if (ds < NCH - 1) {
#pragma unroll
                for (int q = 0; q < 4; q++)
                    bn[q] = *(const float4*)(bBase + (ds + 1) * CH + q * 4);
            }
#pragma unroll 16
            for (int dd = 0; dd < CH; dd++) {
                // A: one lane-consecutive LDS.128 (4 rows), dup via 4 movs
                float4 af = *(const float4*)&sh.A[ds * CH + dd][rowb];
                u64 ad[4] = { pack2f(af.x, af.x), pack2f(af.y, af.y),
                              pack2f(af.z, af.z), pack2f(af.w, af.w) };
                // B: 4 warp-uniform LDS.128 -> 8 natural cw-pair u64s
                const ulonglong2* bp = (const ulonglong2*)&sh.B[cur][dd][cwg * 16];
                ulonglong2 b0 = bp[0], b1 = bp[1], b2 = bp[2], b3 = bp[3];
                u64 bb[8] = { b0.x, b0.y, b1.x, b1.y, b2.x, b2.y, b3.x, b3.y };
#pragma unroll
                for (int r = 0; r < 4; r++)
#pragma unroll
                    for (int j = 0; j < 8; j++)
                        ffma2(acc2[r][j], ad[r], bb[j]);
            }
            if (ds < NCH - 1) {
#pragma unroll
                for (int q = 0; q < 4; q++) {
                    sh.B[nxt][lh + q * 4 + 0][lcw] = bn[q].x;
                    sh.B[nxt][lh + q * 4 + 1][lcw] = bn[q].y;
                    sh.B[nxt][lh + q * 4 + 2][lcw] = bn[q].z;
                    sh.B[nxt][lh + q * 4 + 3][lcw] = bn[q].w;
                }
                __syncthreads();
            }
        }

        // ---- scores replicate reference ((rr - 2*dot) + ee); local top2 ----
        float en[16];
#pragma unroll
        for (int j = 0; j < 16; j++)
            en[j] = __ldg(&g_enorm[STAGE * KCB + n0 + cwg * 16 + j]);

        u64 pb0[4], pb1[4];
#pragma unroll
        for (int r = 0; r < 4; r++) {
            u64 x0 = UMAX64, x1 = UMAX64;
#pragma unroll
            for (int j = 0; j < 8; j++) {
                float dlo, dhi;
                unpack2f(acc2[r][j], dlo, dhi);
                float slo = (rrv[r] - 2.0f * dlo) + en[2 * j];
                float shi = (rrv[r] - 2.0f * dhi) + en[2 * j + 1];
                unsigned idx = (unsigned)(n0 + cwg * 16 + 2 * j);
                top2(((u64)fkey(slo) << 32) | idx,       x0, x1);
                top2(((u64)fkey(shi) << 32) | (idx + 1), x0, x1);
            }
            pb0[r] = x0; pb1[r] = x1;
        }

        // pass 1: per-stripe top1s -> global top1 t0 + 2nd-min-of-b0s t1
        __syncthreads();   // mainloop B reads done; Red safe to write
#pragma unroll
        for (int r = 0; r < 4; r++) sh.Red[rowb + r][cwg] = pb0[r];
        __syncthreads();
        u64 t0 = UMAX64, t1 = UMAX64; int sstar = 0;
        if (tid < 128) {
#pragma unroll
            for (int t = 0; t < 8; t++) top2(sh.Red[tid][t], t0, t1);
            sstar = (int)((t0 & 127u) >> 4);   // winner cw-group
        }
        __syncthreads();
        // pass 2: per-stripe runner-ups; exact top2 = min(t1, b1[winner])
#pragma unroll
        for (int r = 0; r < 4; r++) sh.Red[rowb + r][cwg] = pb1[r];
        __syncthreads();
        if (tid < 128) {
            u64 w = sh.Red[tid][sstar];
            if (w < t1) t1 = w;
            top2(t0, best0, best1);
            top2(t1, best0, best1);
        }
    }

    __syncthreads();
    if (tid < 128) {
        sh.Ridx[tid]  = (int)(best0 & 0xFFFFFFFFull);
        sh.Ridx2[tid] = (int)(best1 & 0xFFFFFFFFull);
    }
    __syncthreads();

    // ---- double-precision rescue + residual update + loss ----
    const int row = tid >> 1;
    const int h   = (tid & 1) * 64;
    const int i1  = sh.Ridx[row];
    const int i2  = sh.Ridx2[row];
    const float* rv = rin + (size_t)(m0 + row) * DIM + h;
    const float* e1 = cb + (size_t)i1 * DIM + h;
    const float* e2 = cb + (size_t)i2 * DIM + h;

    double d1 = 0.0, d2 = 0.0;
#pragma unroll
    for (int c = 0; c < 16; c++) {
        float4 r4 = *(const float4*)(rv + c * 4);
        float4 q1 = *(const float4*)(e1 + c * 4);
        float4 q2 = *(const float4*)(e2 + c * 4);
        d1 = fma((double)r4.x, (double)q1.x, d1);
        d1 = fma((double)r4.y, (double)q1.y, d1);
        d1 = fma((double)r4.z, (double)q1.z, d1);
        d1 = fma((double)r4.w, (double)q1.w, d1);
        d2 = fma((double)r4.x, (double)q2.x, d2);
        d2 = fma((double)r4.y, (double)q2.y, d2);
        d2 = fma((double)r4.z, (double)q2.z, d2);
        d2 = fma((double)r4.w, (double)q2.w, d2);
    }
    d1 += __shfl_xor_sync(0xffffffffu, d1, 1);
    d2 += __shfl_xor_sync(0xffffffffu, d2, 1);

    const float rr = sh.rrS[row];
    const float s1 = (rr - 2.0f * (float)d1) + __ldg(&g_enorm[STAGE * KCB + i1]);
    const float s2 = (rr - 2.0f * (float)d2) + __ldg(&g_enorm[STAGE * KCB + i2]);
    int cidx;
    if (s1 < s2)      cidx = i1;
    else if (s2 < s1) cidx = i2;
    else              cidx = (i1 < i2) ? i1 : i2;

    if ((tid & 1) == 0)
        out[(size_t)NROWS * DIM + 1 + (size_t)(m0 + row) * QSTAGES + STAGE] = (float)cidx;

    const float* qv = cb + (size_t)cidx * DIM + h;
    double lsum = 0.0;
#pragma unroll
    for (int c = 0; c < 16; c++) {
        float4 q = *(const float4*)(qv + c * 4);
        float4 r = *(const float4*)(rv + c * 4);
        float4 rn;
        rn.x = r.x - q.x; rn.y = r.y - q.y; rn.z = r.z - q.z; rn.w = r.w - q.w;
        lsum += (double)rn.x * rn.x + (double)rn.y * rn.y +
                (double)rn.z * rn.z + (double)rn.w * rn.w;
        if (STAGE < QSTAGES - 1) {
            *(float4*)(g_resid + (size_t)(m0 + row) * DIM + h + c * 4) = rn;
        } else {
            const float4 xx = *(const float4*)(x + (size_t)(m0 + row) * DIM + h + c * 4);
            float4 xq;
            xq.x = xx.x - rn.x; xq.y = xx.y - rn.y;
            xq.z = xx.z - rn.z; xq.w = xx.w - rn.w;
            *(float4*)(out + (size_t)(m0 + row) * DIM + h + c * 4) = xq;
        }
    }
#pragma unroll
    for (int off = 16; off; off >>= 1) lsum += __shfl_down_sync(0xffffffffu, lsum, off);
    if ((tid & 31) == 0) atomicAdd(&g_loss[STAGE], lsum);
}

// ---------------------------------------------------------------------------
__global__ void rvq_finalize_kernel(float* __restrict__ out) {
    if (threadIdx.x == 0) {
        double s = 0.0;
        for (int i = 0; i < QSTAGES; i++) s += g_loss[i];
        double mean = (1.0 + BETA) * s / ((double)NROWS * DIM) / (double)QSTAGES;
        out[(size_t)NROWS * DIM] = (float)mean;
    }
}

extern "C" void kernel_launch(void* const* d_in, const int* in_sizes, int n_in,
                              void* d_out, int out_size) {
    const float* x  = (const float*)d_in[0];
    const float* cb = (const float*)d_in[1];
    if (n_in >= 2 && in_sizes[0] == QSTAGES * KCB * DIM && in_sizes[1] == NROWS * DIM) {
        x  = (const float*)d_in[1];
        cb = (const float*)d_in[0];
    }
    float* out = (float*)d_out;

    const int shbytes = (int)sizeof(Sh);
    cudaFuncSetAttribute(rvq_stage_kernel<0>, cudaFuncAttributeMaxDynamicSharedMemorySize, shbytes);
    cudaFuncSetAttribute(rvq_stage_kernel<1>, cudaFuncAttributeMaxDynamicSharedMemorySize, shbytes);
    cudaFuncSetAttribute(rvq_stage_kernel<2>, cudaFuncAttributeMaxDynamicSharedMemorySize, shbytes);
    cudaFuncSetAttribute(rvq_stage_kernel<3>, cudaFuncAttributeMaxDynamicSharedMemorySize, shbytes);

    rvq_prep_kernel<<<512, 256>>>(cb);
    rvq_stage_kernel<0><<<NROWS / BROWS, NTHR, shbytes>>>(x, cb, out);
    rvq_stage_kernel<1><<<NROWS / BROWS, NTHR, shbytes>>>(x, cb, out);
    rvq_stage_kernel<2><<<NROWS / BROWS, NTHR, shbytes>>>(x, cb, out);
    rvq_stage_kernel<3><<<NROWS / BROWS, NTHR, shbytes>>>(x, cb, out);
    rvq_finalize_kernel<<<1, 32>>>(out);
}

// round 16
// speedup vs baseline: 1.0920x; 1.0445x over previous
#include <cuda_runtime.h>
#include <stdint.h>

#define NROWS   131072
#define DIM     128
#define QSTAGES 4
#define KCB     1024
#define BETA    0.25
#define BROWS   128            // rows per block
#define NTHR    256
#define CH      32             // dims per B chunk
#define NCH     (DIM / CH)     // 4 chunks

typedef unsigned long long u64;
#define UMAX64 0xFFFFFFFFFFFFFFFFull

// Scratch (allocation-free rule: __device__ globals)
__device__ float  g_resid[NROWS * DIM];
__device__ float  g_enorm[QSTAGES * KCB];
__device__ double g_loss[QSTAGES];

// Dynamic-smem layout: A resident all 128 dims; B double-buffered 32-dim chunks
struct Sh {
    float A[DIM][BROWS + 4];     // 67.6 KB  [dim][row]
    float B[2][CH][BROWS + 4];   // 33.8 KB  [buf][dim][cw]
    u64   Red[BROWS][9];         //  9.2 KB
    float rrS[BROWS];
    int   Ridx[BROWS];
    int   Ridx2[BROWS];
};

// ---------------------------------------------------------------------------
// packed fp32x2 helpers (Blackwell sm_100+)
// ---------------------------------------------------------------------------
__device__ __forceinline__ u64 pack2f(float lo, float hi) {
    u64 r; asm("mov.b64 %0, {%1, %2};" : "=l"(r) : "f"(lo), "f"(hi)); return r;
}
__device__ __forceinline__ void unpack2f(u64 v, float& lo, float& hi) {
    asm("mov.b64 {%0, %1}, %2;" : "=f"(lo), "=f"(hi) : "l"(v));
}
__device__ __forceinline__ void ffma2(u64& d, u64 a, u64 b) {
    asm("fma.rn.f32x2 %0, %1, %2, %0;" : "+l"(d) : "l"(a), "l"(b));
}
__device__ __forceinline__ unsigned int fkey(float f) {
    unsigned int u = __float_as_uint(f);
    return (u & 0x80000000u) ? ~u : (u | 0x80000000u);
}
__device__ __forceinline__ void top2(u64 k, u64& b0, u64& b1) {
    if (k < b0) { b1 = b0; b0 = k; }
    else if (k < b1) { b1 = k; }
}

// ---------------------------------------------------------------------------
__global__ void rvq_prep_kernel(const float* __restrict__ cb) {
    if (blockIdx.x == 0 && threadIdx.x < QSTAGES) g_loss[threadIdx.x] = 0.0;
    int wid  = (blockIdx.x * blockDim.x + threadIdx.x) >> 5;
    int lane = threadIdx.x & 31;
    if (wid >= QSTAGES * KCB) return;
    const float* row = cb + (size_t)wid * DIM;
    double s = 0.0;
#pragma unroll
    for (int i = 0; i < 4; i++) {
        double v = (double)row[lane + i * 32];
        s = fma(v, v, s);
    }
#pragma unroll
    for (int off = 16; off; off >>= 1) s += __shfl_down_sync(0xffffffffu, s, off);
    if (lane == 0) g_enorm[wid] = (float)s;
}

// ---------------------------------------------------------------------------
// One RVQ stage. 256 threads, 128x128 tile, 2 blocks/SM (launch_bounds
// minBlocks=2 -> regs capped at 128). A staged into smem ONCE (fused with
// rr pre-pass); mainloop stages only B. B staging is split into 4 quarters
// interleaved with the FMA stream: each quarter = 1 LDG.128 (next chunk)
// -> 8 dd of FMAs (hides L2 latency) -> 4 STS, so staging holds only 4
// registers instead of 16, freeing regs for fragment pipelining.
// ---------------------------------------------------------------------------
template <int STAGE>
__global__ __launch_bounds__(NTHR, 2)
void rvq_stage_kernel(const float* __restrict__ x,
                      const float* __restrict__ cbq,
                      float* __restrict__ out)
{
    const float* cb  = cbq + (size_t)STAGE * KCB * DIM;
    const float* rin = (STAGE == 0) ? x : (const float*)g_resid;

    extern __shared__ __align__(16) char smem_raw[];
    Sh& sh = *reinterpret_cast<Sh*>(smem_raw);

    const int tid  = threadIdx.x;
    const int m0   = blockIdx.x * BROWS;
    const int lane = tid & 31;
    const int cwg  = tid >> 5;            // warp id = cw group 0..7 (16 cw each)
    const int rowb = lane * 4;            // first of this thread's 4 rows
    const int lcw  = tid & 127;           // B loader codeword
    const int lh   = (tid >> 7) * 16;     // B loader dim offset {0,16}

    // ---- fused pre-pass: stage A into smem + rr per row (double) ----
    {
        const int row = tid >> 1;
        const int h   = (tid & 1) * 64;
        const float* rv = rin + (size_t)(m0 + row) * DIM + h;
        double s = 0.0;
#pragma unroll
        for (int c = 0; c < 16; c++) {
            float4 v = *(const float4*)(rv + c * 4);
            sh.A[h + c * 4 + 0][row] = v.x;
            sh.A[h + c * 4 + 1][row] = v.y;
            sh.A[h + c * 4 + 2][row] = v.z;
            sh.A[h + c * 4 + 3][row] = v.w;
            s = fma((double)v.x, (double)v.x, s);
            s = fma((double)v.y, (double)v.y, s);
            s = fma((double)v.z, (double)v.z, s);
            s = fma((double)v.w, (double)v.w, s);
        }
        s += __shfl_xor_sync(0xffffffffu, s, 1);
        if ((tid & 1) == 0) sh.rrS[row] = (float)s;
    }
    __syncthreads();

    float rrv[4];
#pragma unroll
    for (int r = 0; r < 4; r++) rrv[r] = sh.rrS[rowb + r];

    u64 best0 = UMAX64, best1 = UMAX64;   // per-row global top2 (tid<128: row=tid)

    for (int nt = 0; nt < KCB / 128; nt++) {
        const int n0 = nt * 128;
        u64 acc2[4][8];                    // [row][cw-pair]
#pragma unroll
        for (int r = 0; r < 4; r++)
#pragma unroll
            for (int j = 0; j < 8; j++) acc2[r][j] = 0ull;

        const float* bBase = cb + (size_t)(n0 + lcw) * DIM + lh;

        // preload B chunk 0 into buffer 0 (conflict-free row-contiguous)
        {
#pragma unroll
            for (int q = 0; q < 4; q++) {
                float4 b = *(const float4*)(bBase + q * 4);
                sh.B[0][lh + q * 4 + 0][lcw] = b.x;
                sh.B[0][lh + q * 4 + 1][lcw] = b.y;
                sh.B[0][lh + q * 4 + 2][lcw] = b.z;
                sh.B[0][lh + q * 4 + 3][lcw] = b.w;
            }
        }
        __syncthreads();

#pragma unroll 1
        for (int ds = 0; ds < NCH; ds++) {
            const int cur = ds & 1, nxt = cur ^ 1;
#pragma unroll
            for (int qq = 0; qq < 4; qq++) {
                // stage quarter qq of NEXT chunk: 1 LDG, live 4 regs
                float4 bq;
                if (ds < NCH - 1)
                    bq = *(const float4*)(bBase + (ds + 1) * CH + qq * 4);
#pragma unroll
                for (int d2 = 0; d2 < 8; d2++) {
                    const int dd = qq * 8 + d2;
                    // A: one lane-consecutive LDS.128 (4 rows), dup via 4 movs
                    float4 af = *(const float4*)&sh.A[ds * CH + dd][rowb];
                    u64 ad[4] = { pack2f(af.x, af.x), pack2f(af.y, af.y),
                                  pack2f(af.z, af.z), pack2f(af.w, af.w) };
                    // B: 4 warp-uniform LDS.128 -> 8 natural cw-pair u64s
                    const ulonglong2* bp =
                        (const ulonglong2*)&sh.B[cur][dd][cwg * 16];
                    ulonglong2 b0 = bp[0], b1 = bp[1], b2 = bp[2], b3 = bp[3];
                    u64 bb[8] = { b0.x, b0.y, b1.x, b1.y,
                                  b2.x, b2.y, b3.x, b3.y };
#pragma unroll
                    for (int r = 0; r < 4; r++)
#pragma unroll
                        for (int j = 0; j < 8; j++)
                            ffma2(acc2[r][j], ad[r], bb[j]);
                }
                if (ds < NCH - 1) {
                    sh.B[nxt][lh + qq * 4 + 0][lcw] = bq.x;
                    sh.B[nxt][lh + qq * 4 + 1][lcw] = bq.y;
                    sh.B[nxt][lh + qq * 4 + 2][lcw] = bq.z;
                    sh.B[nxt][lh + qq * 4 + 3][lcw] = bq.w;
                }
            }
            if (ds < NCH - 1) __syncthreads();
        }

        // ---- scores replicate reference ((rr - 2*dot) + ee); local top2 ----
        float en[16];
#pragma unroll
        for (int j = 0; j < 16; j++)
            en[j] = __ldg(&g_enorm[STAGE * KCB + n0 + cwg * 16 + j]);

        u64 pb0[4], pb1[4];
#pragma unroll
        for (int r = 0; r < 4; r++) {
            u64 x0 = UMAX64, x1 = UMAX64;
#pragma unroll
            for (int j = 0; j < 8; j++) {
                float dlo, dhi;
                unpack2f(acc2[r][j], dlo, dhi);
                float slo = (rrv[r] - 2.0f * dlo) + en[2 * j];
                float shi = (rrv[r] - 2.0f * dhi) + en[2 * j + 1];
                unsigned idx = (unsigned)(n0 + cwg * 16 + 2 * j);
                top2(((u64)fkey(slo) << 32) | idx,       x0, x1);
                top2(((u64)fkey(shi) << 32) | (idx + 1), x0, x1);
            }
            pb0[r] = x0; pb1[r] = x1;
        }

        // pass 1: per-stripe top1s -> global top1 t0 + 2nd-min-of-b0s t1
        __syncthreads();   // mainloop B reads done; Red safe to write
#pragma unroll
        for (int r = 0; r < 4; r++) sh.Red[rowb + r][cwg] = pb0[r];
        __syncthreads();
        u64 t0 = UMAX64, t1 = UMAX64; int sstar = 0;
        if (tid < 128) {
#pragma unroll
            for (int t = 0; t < 8; t++) top2(sh.Red[tid][t], t0, t1);
            sstar = (int)((t0 & 127u) >> 4);   // winner cw-group
        }
        __syncthreads();
        // pass 2: per-stripe runner-ups; exact top2 = min(t1, b1[winner])
#pragma unroll
        for (int r = 0; r < 4; r++) sh.Red[rowb + r][cwg] = pb1[r];
        __syncthreads();
        if (tid < 128) {
            u64 w = sh.Red[tid][sstar];
            if (w < t1) t1 = w;
            top2(t0, best0, best1);
            top2(t1, best0, best1);
        }
    }

    __syncthreads();
    if (tid < 128) {
        sh.Ridx[tid]  = (int)(best0 & 0xFFFFFFFFull);
        sh.Ridx2[tid] = (int)(best1 & 0xFFFFFFFFull);
    }
    __syncthreads();

    // ---- double-precision rescue + residual update + loss ----
    const int row = tid >> 1;
    const int h   = (tid & 1) * 64;
    const int i1  = sh.Ridx[row];
    const int i2  = sh.Ridx2[row];
    const float* rv = rin + (size_t)(m0 + row) * DIM + h;
    const float* e1 = cb + (size_t)i1 * DIM + h;
    const float* e2 = cb + (size_t)i2 * DIM + h;

    double d1 = 0.0, d2 = 0.0;
#pragma unroll
    for (int c = 0; c < 16; c++) {
        float4 r4 = *(const float4*)(rv + c * 4);
        float4 q1 = *(const float4*)(e1 + c * 4);
        float4 q2 = *(const float4*)(e2 + c * 4);
        d1 = fma((double)r4.x, (double)q1.x, d1);
        d1 = fma((double)r4.y, (double)q1.y, d1);
        d1 = fma((double)r4.z, (double)q1.z, d1);
        d1 = fma((double)r4.w, (double)q1.w, d1);
        d2 = fma((double)r4.x, (double)q2.x, d2);
        d2 = fma((double)r4.y, (double)q2.y, d2);
        d2 = fma((double)r4.z, (double)q2.z, d2);
        d2 = fma((double)r4.w, (double)q2.w, d2);
    }
    d1 += __shfl_xor_sync(0xffffffffu, d1, 1);
    d2 += __shfl_xor_sync(0xffffffffu, d2, 1);

    const float rr = sh.rrS[row];
    const float s1 = (rr - 2.0f * (float)d1) + __ldg(&g_enorm[STAGE * KCB + i1]);
    const float s2 = (rr - 2.0f * (float)d2) + __ldg(&g_enorm[STAGE * KCB + i2]);
    int cidx;
    if (s1 < s2)      cidx = i1;
    else if (s2 < s1) cidx = i2;
    else              cidx = (i1 < i2) ? i1 : i2;

    if ((tid & 1) == 0)
        out[(size_t)NROWS * DIM + 1 + (size_t)(m0 + row) * QSTAGES + STAGE] = (float)cidx;

    const float* qv = cb + (size_t)cidx * DIM + h;
    double lsum = 0.0;
#pragma unroll
    for (int c = 0; c < 16; c++) {
        float4 q = *(const float4*)(qv + c * 4);
        float4 r = *(const float4*)(rv + c * 4);
        float4 rn;
        rn.x = r.x - q.x; rn.y = r.y - q.y; rn.z = r.z - q.z; rn.w = r.w - q.w;
        lsum += (double)rn.x * rn.x + (double)rn.y * rn.y +
                (double)rn.z * rn.z + (double)rn.w * rn.w;
        if (STAGE < QSTAGES - 1) {
            *(float4*)(g_resid + (size_t)(m0 + row) * DIM + h + c * 4) = rn;
        } else {
            const float4 xx = *(const float4*)(x + (size_t)(m0 + row) * DIM + h + c * 4);
            float4 xq;
            xq.x = xx.x - rn.x; xq.y = xx.y - rn.y;
            xq.z = xx.z - rn.z; xq.w = xx.w - rn.w;
            *(float4*)(out + (size_t)(m0 + row) * DIM + h + c * 4) = xq;
        }
    }
#pragma unroll
    for (int off = 16; off; off >>= 1) lsum += __shfl_down_sync(0xffffffffu, lsum, off);
    if ((tid & 31) == 0) atomicAdd(&g_loss[STAGE], lsum);
}

// ---------------------------------------------------------------------------
__global__ void rvq_finalize_kernel(float* __restrict__ out) {
    if (threadIdx.x == 0) {
        double s = 0.0;
        for (int i = 0; i < QSTAGES; i++) s += g_loss[i];
        double mean = (1.0 + BETA) * s / ((double)NROWS * DIM) / (double)QSTAGES;
        out[(size_t)NROWS * DIM] = (float)mean;
    }
}

extern "C" void kernel_launch(void* const* d_in, const int* in_sizes, int n_in,
                              void* d_out, int out_size) {
    const float* x  = (const float*)d_in[0];
    const float* cb = (const float*)d_in[1];
    if (n_in >= 2 && in_sizes[0] == QSTAGES * KCB * DIM && in_sizes[1] == NROWS * DIM) {
        x  = (const float*)d_in[1];
        cb = (const float*)d_in[0];
    }
    float* out = (float*)d_out;

    const int shbytes = (int)sizeof(Sh);
    cudaFuncSetAttribute(rvq_stage_kernel<0>, cudaFuncAttributeMaxDynamicSharedMemorySize, shbytes);
    cudaFuncSetAttribute(rvq_stage_kernel<1>, cudaFuncAttributeMaxDynamicSharedMemorySize, shbytes);
    cudaFuncSetAttribute(rvq_stage_kernel<2>, cudaFuncAttributeMaxDynamicSharedMemorySize, shbytes);
    cudaFuncSetAttribute(rvq_stage_kernel<3>, cudaFuncAttributeMaxDynamicSharedMemorySize, shbytes);

    rvq_prep_kernel<<<512, 256>>>(cb);
    rvq_stage_kernel<0><<<NROWS / BROWS, NTHR, shbytes>>>(x, cb, out);
    rvq_stage_kernel<1><<<NROWS / BROWS, NTHR, shbytes>>>(x, cb, out);
    rvq_stage_kernel<2><<<NROWS / BROWS, NTHR, shbytes>>>(x, cb, out);
    rvq_stage_kernel<3><<<NROWS / BROWS, NTHR, shbytes>>>(x, cb, out);
    rvq_finalize_kernel<<<1, 32>>>(out);
}